// round 6
// baseline (speedup 1.0000x reference)
#include <cuda_runtime.h>
#include <cstdint>

#define NN 1024
#define H2 60
#define DEP 10
#define DOUT 70
#define NTYPE 50
#define TSTRIDE 72            // T row stride in floats (288 bytes)
#define ROWBYTES (TSTRIDE*4)  // 288
#define TBYTES (NTYPE*ROWBYTES)  // 14400 bytes per i

// Scratch (static device array — no allocation)
__device__ float g_T[NN * NTYPE * TSTRIDE];   // 14.75 MB

// tanh(x) = 1 - 2/(exp(2x)+1), via SFU ex2/rcp.
__device__ __forceinline__ float fast_tanh(float x) {
    float e, r;
    asm("ex2.approx.f32 %0, %1;" : "=f"(e) : "f"(x * 2.885390082f)); // 2*log2(e)
    asm("rcp.approx.f32 %0, %1;" : "=f"(r) : "f"(e + 1.0f));
    return fmaf(-2.0f, r, 1.0f);
}

// ---------------------------------------------------------------------------
// Kernel R (block = row i, 256 threads): masked type histogram, hW projection,
// T table (tanh) with the t-loop split across two thread halves, s_in,
// and zero s_out row i.
// ---------------------------------------------------------------------------
__global__ __launch_bounds__(256) void row_kernel(
    const float* __restrict__ h,
    const float* __restrict__ emb,
    const float* __restrict__ W,
    const float* __restrict__ bvec,
    const int* __restrict__ matrix,
    const int* __restrict__ mask,
    float* __restrict__ out)      // [0..N*DOUT) = s_in, [N*DOUT..) = s_out
{
    const int i = blockIdx.x;
    const int tid = threadIdx.x;
    const int w = tid >> 5;

    __shared__ int   cnt[8][64];        // warp-private histograms (padded)
    __shared__ float hsh[H2];
    __shared__ float esh[NTYPE * DEP];  // 500 floats
    __shared__ float sA[DOUT];          // partial s_in from half 0

    for (int k = tid; k < 8 * 64; k += 256) ((int*)cnt)[k] = 0;
    if (tid < H2) hsh[tid] = h[i * H2 + tid];
    for (int k = tid; k < NTYPE * DEP; k += 256) esh[k] = emb[k];
    __syncthreads();

    // masked type histogram (int4 loads, warp-private counters)
    const int4* m4 = (const int4*)(matrix + (size_t)i * 2 * NN);
    const int4* k4 = (const int4*)(mask   + (size_t)i * 2 * NN);
    for (int e = tid; e < 512; e += 256) {
        int4 mm = m4[e];
        int4 kk = k4[e];
        if (kk.x) atomicAdd(&cnt[w][mm.x], 1);
        if (kk.y) atomicAdd(&cnt[w][mm.y], 1);
        if (kk.z) atomicAdd(&cnt[w][mm.z], 1);
        if (kk.w) atomicAdd(&cnt[w][mm.w], 1);
    }
    __syncthreads();
    if (tid < NTYPE) {
        int s = cnt[0][tid];
        #pragma unroll
        for (int b = 1; b < 8; b++) s += cnt[b][tid];
        cnt[0][tid] = s;
    }
    __syncthreads();

    const int half = tid >> 7;        // 0 or 1
    const int f = tid & 127;
    float acc = 0.f;
    if (f < DOUT) {
        float hw = 0.f;
        #pragma unroll 6
        for (int c = 0; c < H2; c++) hw = fmaf(hsh[c], W[c * DOUT + f], hw);
        float Wc[DEP];
        #pragma unroll
        for (int c = 0; c < DEP; c++) Wc[c] = W[(H2 + c) * DOUT + f];
        const float bf = bvec[f];

        const int t0 = half * (NTYPE / 2), t1 = t0 + NTYPE / 2;
        float* Trow = g_T + (size_t)i * NTYPE * TSTRIDE + f;
        #pragma unroll 5
        for (int t = t0; t < t1; t++) {
            float ew = bf;
            #pragma unroll
            for (int c = 0; c < DEP; c++) ew = fmaf(esh[t * DEP + c], Wc[c], ew);
            float v = fast_tanh(hw + ew);
            Trow[t * TSTRIDE] = v;
            acc = fmaf((float)cnt[0][t], v, acc);
        }
        if (half == 0) sA[f] = acc;
    }
    __syncthreads();
    if (half == 1 && f < DOUT) {
        out[i * DOUT + f] = sA[f] + acc;        // s_in
        out[NN * DOUT + i * DOUT + f] = 0.f;    // zero s_out row i for kernel C
    }
}

// ---------------------------------------------------------------------------
// Kernel C: s_out gather. Grid (8 j-tiles, 37 i-tiles) = 296 blocks,
// 2 CTAs/SM. cp.async ping-pong staging of T[i] (50x288B). Codes carry
// pre-scaled byte offsets (type*288) or 0xFFFF sentinel; the gather is a
// predicated ld.shared (no wavefront when the mask bit was off).
// Lane L covers dims (2L, 2L+1) as float2; all lanes also load a "tail"
// float at row+256+4L (only lanes 0..5 are meaningful; the rest accumulate
// garbage into a never-stored register — a 32-float pad keeps reads in bounds).
// ---------------------------------------------------------------------------
#define JT 128
#define IT 28
#define CTHREADS 512
#define JPW 8   // JT / 16 warps
#define TPAD 32
#define TBUF (NTYPE * TSTRIDE + TPAD)   // floats per staging buffer

__device__ __forceinline__ void cp16(unsigned dst, const void* src) {
    asm volatile("cp.async.cg.shared.global [%0], [%1], 16;" :: "r"(dst), "l"(src));
}

__device__ __forceinline__ void gather_row(unsigned off, unsigned addr2, unsigned addrT,
                                           float& ax, float& ay, float& az) {
    asm volatile("{\n\t"
        ".reg .pred p;\n\t"
        ".reg .f32 x, y, z;\n\t"
        "setp.lt.u32 p, %3, 14400;\n\t"
        "@p ld.shared.v2.f32 {x, y}, [%4];\n\t"
        "@p ld.shared.f32 z, [%5];\n\t"
        "@p add.f32 %0, %0, x;\n\t"
        "@p add.f32 %1, %1, y;\n\t"
        "@p add.f32 %2, %2, z;\n\t"
        "}" : "+f"(ax), "+f"(ay), "+f"(az)
            : "r"(off), "r"(addr2), "r"(addrT));
}

__global__ __launch_bounds__(CTHREADS, 2) void col_kernel(
    const int* __restrict__ matrix,
    const int* __restrict__ mask,
    float* __restrict__ sout)   // out + N*DOUT, zeroed by row_kernel
{
    __shared__ float Tsh[2][TBUF];
    __shared__ int   codes[2][JT];

    const int jbase = blockIdx.x * JT;
    const int i0 = blockIdx.y * IT;
    const int i1 = min(i0 + IT, NN);
    const int tid = threadIdx.x;
    const int w = tid >> 5, lane = tid & 31;

    float2 a0[JPW];
    float  a1[JPW];
    #pragma unroll
    for (int q = 0; q < JPW; q++) { a0[q] = make_float2(0.f, 0.f); a1[q] = 0.f; }

    const unsigned ts0 = (unsigned)__cvta_generic_to_shared(&Tsh[0][0]);
    const unsigned ts1 = (unsigned)__cvta_generic_to_shared(&Tsh[1][0]);
    // per-buffer lane bases: float2 part and tail part
    const unsigned b2_0 = ts0 + lane * 8, b2_1 = ts1 + lane * 8;
    const unsigned bt_0 = ts0 + 256 + lane * 4, bt_1 = ts1 + 256 + lane * 4;

    // prologue: stage i0 (50 rows = 900 float4)
    {
        const float4* src = (const float4*)(g_T + (size_t)i0 * NTYPE * TSTRIDE);
        cp16(ts0 + tid * 16, src + tid);
        if (tid < 388) cp16(ts0 + (512 + tid) * 16, src + 512 + tid);
        asm volatile("cp.async.commit_group;");
    }
    int pcode = 0;
    if (tid < JT) {
        int j = jbase + tid;
        int2 tt = ((const int2*)matrix)[(size_t)i0 * NN + j];
        int2 mm = ((const int2*)mask)[(size_t)i0 * NN + j];
        pcode = (mm.x ? tt.x * ROWBYTES : 0xFFFF) |
                ((mm.y ? tt.y * ROWBYTES : 0xFFFF) << 16);
    }

    for (int i = i0; i < i1; i++) {
        const int buf = (i - i0) & 1;

        asm volatile("cp.async.wait_group 0;" ::: "memory");  // T[i] landed
        if (tid < JT) codes[buf][tid] = pcode;
        __syncthreads();   // T[i]+codes[i] visible; gathers of i-1 from buf^1 done

        if (i + 1 < i1) {
            const float4* src = (const float4*)(g_T + (size_t)(i + 1) * NTYPE * TSTRIDE);
            const unsigned dst = buf ? ts0 : ts1;
            cp16(dst + tid * 16, src + tid);
            if (tid < 388) cp16(dst + (512 + tid) * 16, src + 512 + tid);
            asm volatile("cp.async.commit_group;");
            if (tid < JT) {
                int j = jbase + tid;
                int2 tt = ((const int2*)matrix)[(size_t)(i + 1) * NN + j];
                int2 mm = ((const int2*)mask)[(size_t)(i + 1) * NN + j];
                pcode = (mm.x ? tt.x * ROWBYTES : 0xFFFF) |
                        ((mm.y ? tt.y * ROWBYTES : 0xFFFF) << 16);
            }
        }

        // predicated gather for row i
        const unsigned b2 = buf ? b2_1 : b2_0;
        const unsigned bt = buf ? bt_1 : bt_0;
        const int* cb = codes[buf];
        const int jb = w * JPW;
        #pragma unroll
        for (int q = 0; q < JPW; q++) {
            unsigned code = (unsigned)cb[jb + q];   // warp-uniform broadcast
            unsigned off0 = code & 0xFFFFu;
            unsigned off1 = code >> 16;
            gather_row(off0, b2 + off0, bt + off0, a0[q].x, a0[q].y, a1[q]);
            gather_row(off1, b2 + off1, bt + off1, a0[q].x, a0[q].y, a1[q]);
        }
    }

    // combine partials across the 37 i-tiles (vector reductions)
    #pragma unroll
    for (int q = 0; q < JPW; q++) {
        int j = jbase + w * JPW + q;
        float* base = sout + (size_t)j * DOUT;
        asm volatile("red.global.add.v2.f32 [%0], {%1, %2};"
                     :: "l"(base + 2 * lane), "f"(a0[q].x), "f"(a0[q].y) : "memory");
        if (lane < 6) atomicAdd(base + 64 + lane, a1[q]);
    }
}

// ---------------------------------------------------------------------------
extern "C" void kernel_launch(void* const* d_in, const int* in_sizes, int n_in,
                              void* d_out, int out_size)
{
    const float* h      = (const float*)d_in[0];
    const float* emb    = (const float*)d_in[1];
    const float* W      = (const float*)d_in[2];
    const float* bvec   = (const float*)d_in[3];
    const int*   matrix = (const int*)d_in[4];
    const int*   mask   = (const int*)d_in[5];
    float* out = (float*)d_out;

    row_kernel<<<NN, 256>>>(h, emb, W, bvec, matrix, mask, out);
    col_kernel<<<dim3(8, 37), CTHREADS>>>(matrix, mask, out + NN * DOUT);
}

// round 7
// speedup vs baseline: 1.6448x; 1.6448x over previous
#include <cuda_runtime.h>
#include <cstdint>

#define NN 1024
#define H2 60
#define DEP 10
#define DOUT 70
#define NTYPE 50

// T split: main = dims 0..63, row stride 64 floats (256B, 128B-aligned rows)
//          tail = dims 64..69, row stride 9 floats (36B, bank-spreading)
#define MAINF 3200            // 50*64 floats per i (main)
#define TAILS 480             // tail floats per i in global (50*9=450 used, padded)
#define MSENT 3200            // smem float idx of main sentinel row (64 zero floats)
#define TAILB 3264            // smem float idx of tail region
#define BUFV  3728            // smem floats per buffer (3264 + 459 + pad)
#define SENTOFF 12800u        // byte offset code for masked slot (= 50*256)

__device__ float g_Tm[NN * MAINF];   // 13.1 MB
__device__ float g_Tt[NN * TAILS];   // 1.97 MB

// tanh(x) = 1 - 2/(exp(2x)+1), via SFU ex2/rcp.
__device__ __forceinline__ float fast_tanh(float x) {
    float e, r;
    asm("ex2.approx.f32 %0, %1;" : "=f"(e) : "f"(x * 2.885390082f));
    asm("rcp.approx.f32 %0, %1;" : "=f"(r) : "f"(e + 1.0f));
    return fmaf(-2.0f, r, 1.0f);
}

// ---------------------------------------------------------------------------
// Kernel R (block = row i, 256 threads): masked type histogram, hW projection,
// T table (split main/tail), s_in, zero s_out row i.
// ---------------------------------------------------------------------------
__global__ __launch_bounds__(256) void row_kernel(
    const float* __restrict__ h,
    const float* __restrict__ emb,
    const float* __restrict__ W,
    const float* __restrict__ bvec,
    const int* __restrict__ matrix,
    const int* __restrict__ mask,
    float* __restrict__ out)
{
    const int i = blockIdx.x;
    const int tid = threadIdx.x;
    const int w = tid >> 5;

    __shared__ int   cnt[8][64];
    __shared__ float hsh[H2];
    __shared__ float esh[NTYPE * DEP];
    __shared__ float sA[DOUT];

    for (int k = tid; k < 8 * 64; k += 256) ((int*)cnt)[k] = 0;
    if (tid < H2) hsh[tid] = h[i * H2 + tid];
    for (int k = tid; k < NTYPE * DEP; k += 256) esh[k] = emb[k];
    __syncthreads();

    const int4* m4 = (const int4*)(matrix + (size_t)i * 2 * NN);
    const int4* k4 = (const int4*)(mask   + (size_t)i * 2 * NN);
    for (int e = tid; e < 512; e += 256) {
        int4 mm = m4[e];
        int4 kk = k4[e];
        if (kk.x) atomicAdd(&cnt[w][mm.x], 1);
        if (kk.y) atomicAdd(&cnt[w][mm.y], 1);
        if (kk.z) atomicAdd(&cnt[w][mm.z], 1);
        if (kk.w) atomicAdd(&cnt[w][mm.w], 1);
    }
    __syncthreads();
    if (tid < NTYPE) {
        int s = cnt[0][tid];
        #pragma unroll
        for (int b = 1; b < 8; b++) s += cnt[b][tid];
        cnt[0][tid] = s;
    }
    __syncthreads();

    const int half = tid >> 7;
    const int f = tid & 127;
    float acc = 0.f;
    if (f < DOUT) {
        float hw = 0.f;
        #pragma unroll 6
        for (int c = 0; c < H2; c++) hw = fmaf(hsh[c], W[c * DOUT + f], hw);
        float Wc[DEP];
        #pragma unroll
        for (int c = 0; c < DEP; c++) Wc[c] = W[(H2 + c) * DOUT + f];
        const float bf = bvec[f];

        const int t0 = half * (NTYPE / 2), t1 = t0 + NTYPE / 2;
        #pragma unroll 5
        for (int t = t0; t < t1; t++) {
            float ew = bf;
            #pragma unroll
            for (int c = 0; c < DEP; c++) ew = fmaf(esh[t * DEP + c], Wc[c], ew);
            float v = fast_tanh(hw + ew);
            if (f < 64) g_Tm[(size_t)i * MAINF + t * 64 + f] = v;
            else        g_Tt[(size_t)i * TAILS + t * 9 + (f - 64)] = v;
            acc = fmaf((float)cnt[0][t], v, acc);
        }
        if (half == 0) sA[f] = acc;
    }
    __syncthreads();
    if (half == 1 && f < DOUT) {
        out[i * DOUT + f] = sA[f] + acc;        // s_in
        out[NN * DOUT + i * DOUT + f] = 0.f;    // zero s_out for kernel C
    }
}

// ---------------------------------------------------------------------------
// Kernel C: s_out gather. Grid (8 j-tiles of 128, 37 i-tiles) = 296 blocks,
// 2 CTAs/SM. cp.async ping-pong stages T[i] (main 12.8KB + tail 1.8KB).
// Codes live in registers (lane<8 holds its warp's 8 j-codes, prefetched one
// i ahead via LDG) and are broadcast by shfl — no SMEM code traffic.
// Main: warp reads row float2 per lane (dims 0..63, 2 wf). Masked slot reads
// the 64-float zero sentinel row. Tail: 4 slots per read, lane=(g=lane>>3,
// d=lane&7), dims 64..69 (d>=6 lanes accumulate garbage, never stored).
// ---------------------------------------------------------------------------
#define IT 28
#define CTHREADS 512

__device__ __forceinline__ void cp16(unsigned dst, const void* src) {
    asm volatile("cp.async.cg.shared.global [%0], [%1], 16;" :: "r"(dst), "l"(src));
}
__device__ __forceinline__ void cp8(unsigned dst, const void* src) {
    asm volatile("cp.async.ca.shared.global [%0], [%1], 8;" :: "r"(dst), "l"(src));
}

__global__ __launch_bounds__(CTHREADS, 2) void col_kernel(
    const int* __restrict__ matrix,
    const int* __restrict__ mask,
    float* __restrict__ sout)
{
    __shared__ float Tsh[2][BUFV];

    const int jbase = blockIdx.x * 128;
    const int i0 = blockIdx.y * IT;
    const int i1 = min(i0 + IT, NN);
    const int tid = threadIdx.x;
    const int w = tid >> 5, lane = tid & 31;
    const int g = lane >> 3, d = lane & 7;

    float2 a0[8];
    float  a1[4];
    #pragma unroll
    for (int q = 0; q < 8; q++) a0[q] = make_float2(0.f, 0.f);
    #pragma unroll
    for (int r = 0; r < 4; r++) a1[r] = 0.f;

    // zero sentinel regions of both buffers (never touched by cp.async)
    if (tid < 64) { Tsh[0][MSENT + tid] = 0.f; Tsh[1][MSENT + tid] = 0.f; }
    if (tid < 9)  { Tsh[0][TAILB + 450 + tid] = 0.f; Tsh[1][TAILB + 450 + tid] = 0.f; }

    const char* tb0 = (const char*)&Tsh[0][0];
    const char* tb1 = (const char*)&Tsh[1][0];
    const unsigned ts0 = (unsigned)__cvta_generic_to_shared(tb0);
    const unsigned ts1 = (unsigned)__cvta_generic_to_shared(tb1);

    const int2* m2 = (const int2*)matrix;
    const int2* k2 = (const int2*)mask;

    // prologue: stage i0
    {
        const float4* srcM = (const float4*)(g_Tm + (size_t)i0 * MAINF);
        cp16(ts0 + tid * 16, srcM + tid);
        if (tid < 288) cp16(ts0 + (512 + tid) * 16, srcM + 512 + tid);
        const float4* srcT = (const float4*)(g_Tt + (size_t)i0 * TAILS);
        if (tid >= 288 && tid < 400) cp16(ts0 + TAILB * 4 + (tid - 288) * 16, srcT + (tid - 288));
        if (tid == 400) cp8(ts0 + TAILB * 4 + 448 * 4, g_Tt + (size_t)i0 * TAILS + 448);
        asm volatile("cp.async.commit_group;");
    }

    // codes for i0 (lane<8 holds the warp's 8 j-codes)
    unsigned c_cur = 0, c_next = 0;
    if (lane < 8) {
        size_t idx = (size_t)i0 * NN + jbase + w * 8 + lane;
        int2 tt = m2[idx];
        int2 km = k2[idx];
        c_cur = (km.x ? (unsigned)(tt.x << 8) : SENTOFF) |
                ((km.y ? (unsigned)(tt.y << 8) : SENTOFF) << 16);
    }

    for (int i = i0; i < i1; i++) {
        const int buf = (i - i0) & 1;
        const char* Tb = buf ? tb1 : tb0;

        asm volatile("cp.async.wait_group 0;" ::: "memory");  // T[i] landed
        __syncthreads();   // visible to all; gathers of i-1 done before reuse

        if (i + 1 < i1) {
            const unsigned dst = buf ? ts0 : ts1;
            const float4* srcM = (const float4*)(g_Tm + (size_t)(i + 1) * MAINF);
            cp16(dst + tid * 16, srcM + tid);
            if (tid < 288) cp16(dst + (512 + tid) * 16, srcM + 512 + tid);
            const float4* srcT = (const float4*)(g_Tt + (size_t)(i + 1) * TAILS);
            if (tid >= 288 && tid < 400) cp16(dst + TAILB * 4 + (tid - 288) * 16, srcT + (tid - 288));
            if (tid == 400) cp8(dst + TAILB * 4 + 448 * 4, g_Tt + (size_t)(i + 1) * TAILS + 448);
            asm volatile("cp.async.commit_group;");
            if (lane < 8) {
                size_t idx = (size_t)(i + 1) * NN + jbase + w * 8 + lane;
                int2 tt = m2[idx];
                int2 km = k2[idx];
                c_next = (km.x ? (unsigned)(tt.x << 8) : SENTOFF) |
                         ((km.y ? (unsigned)(tt.y << 8) : SENTOFF) << 16);
            }
        }

        // main gather (dims 0..63): 2 rows per j, sentinel row for masked
        const char* mbase = Tb + lane * 8;
        #pragma unroll
        for (int q = 0; q < 8; q++) {
            unsigned cc = __shfl_sync(0xffffffffu, c_cur, q);
            unsigned o0 = cc & 0xFFFFu;
            unsigned o1 = cc >> 16;
            float2 v0 = *(const float2*)(mbase + o0);
            float2 v1 = *(const float2*)(mbase + o1);
            a0[q].x += v0.x + v1.x;
            a0[q].y += v0.y + v1.y;
        }

        // tail gather (dims 64..69): 4 slots per read
        const char* tbase = Tb + TAILB * 4 + d * 4;
        #pragma unroll
        for (int r = 0; r < 4; r++) {
            int slot = r * 4 + g;
            unsigned cc = __shfl_sync(0xffffffffu, c_cur, slot >> 1);
            unsigned c16 = (cc >> ((slot & 1) * 16)) & 0xFFFFu;
            unsigned t = c16 >> 8;                 // type, or 50 for sentinel
            a1[r] += *(const float*)(tbase + t * 36);
        }

        c_cur = c_next;
    }

    // epilogue
    #pragma unroll
    for (int q = 0; q < 8; q++) {
        int j = jbase + w * 8 + q;
        float* base = sout + (size_t)j * DOUT;
        asm volatile("red.global.add.v2.f32 [%0], {%1, %2};"
                     :: "l"(base + 2 * lane), "f"(a0[q].x), "f"(a0[q].y) : "memory");
    }
    if (d < 6) {
        #pragma unroll
        for (int r = 0; r < 4; r++) {
            int j = jbase + w * 8 + ((r * 4 + g) >> 1);
            atomicAdd(sout + (size_t)j * DOUT + 64 + d, a1[r]);
        }
    }
}

// ---------------------------------------------------------------------------
extern "C" void kernel_launch(void* const* d_in, const int* in_sizes, int n_in,
                              void* d_out, int out_size)
{
    const float* h      = (const float*)d_in[0];
    const float* emb    = (const float*)d_in[1];
    const float* W      = (const float*)d_in[2];
    const float* bvec   = (const float*)d_in[3];
    const int*   matrix = (const int*)d_in[4];
    const int*   mask   = (const int*)d_in[5];
    float* out = (float*)d_out;

    row_kernel<<<NN, 256>>>(h, emb, W, bvec, matrix, mask, out);
    col_kernel<<<dim3(8, 37), CTHREADS>>>(matrix, mask, out + NN * DOUT);
}

// round 8
// speedup vs baseline: 2.1011x; 1.2774x over previous
#include <cuda_runtime.h>
#include <cuda_fp16.h>
#include <cstdint>

#define NN 1024
#define H2 60
#define DEP 10
#define DOUT 70
#define NTYPE 50

// fp16 T layout per i: main = dims 0..63, 50 rows x 64 halfs (128B rows);
// tail = dims 64..69 (+2 pad), 50 rows x 8 halfs (16B rows).
// Global block per i = 3200 (main) + 400 (tail) = 3600 halfs = 7200B.
#define TPI 3600
// SMEM buffer (halfs): [0,3200) main rows, [3200,3264) main sentinel (zeros),
// [3264,3664) tail rows, [3664,3672) tail sentinel, pad to 3680 (7360B).
#define BUFH 3680
#define MAIN_SENT_B 6400u     // byte offset of main sentinel row (= 50*128)
#define TAIL_BASE_B 6528      // byte offset of tail region

__device__ __half g_Th[NN * TPI];    // 7.37 MB — L2-resident

// tanh(x) = 1 - 2/(exp(2x)+1), via SFU ex2/rcp.
__device__ __forceinline__ float fast_tanh(float x) {
    float e, r;
    asm("ex2.approx.f32 %0, %1;" : "=f"(e) : "f"(x * 2.885390082f));
    asm("rcp.approx.f32 %0, %1;" : "=f"(r) : "f"(e + 1.0f));
    return fmaf(-2.0f, r, 1.0f);
}

// ---------------------------------------------------------------------------
// Kernel R (block = row i, 256 threads): masked type histogram, hW projection,
// T table (fp16, split main/tail), s_in (fp32), zero s_out row i.
// ---------------------------------------------------------------------------
__global__ __launch_bounds__(256) void row_kernel(
    const float* __restrict__ h,
    const float* __restrict__ emb,
    const float* __restrict__ W,
    const float* __restrict__ bvec,
    const int* __restrict__ matrix,
    const int* __restrict__ mask,
    float* __restrict__ out)
{
    const int i = blockIdx.x;
    const int tid = threadIdx.x;
    const int w = tid >> 5;

    __shared__ int   cnt[8][64];
    __shared__ float hsh[H2];
    __shared__ float esh[NTYPE * DEP];
    __shared__ float sA[DOUT];

    for (int k = tid; k < 8 * 64; k += 256) ((int*)cnt)[k] = 0;
    if (tid < H2) hsh[tid] = h[i * H2 + tid];
    for (int k = tid; k < NTYPE * DEP; k += 256) esh[k] = emb[k];
    __syncthreads();

    const int4* m4 = (const int4*)(matrix + (size_t)i * 2 * NN);
    const int4* k4 = (const int4*)(mask   + (size_t)i * 2 * NN);
    for (int e = tid; e < 512; e += 256) {
        int4 mm = m4[e];
        int4 kk = k4[e];
        if (kk.x) atomicAdd(&cnt[w][mm.x], 1);
        if (kk.y) atomicAdd(&cnt[w][mm.y], 1);
        if (kk.z) atomicAdd(&cnt[w][mm.z], 1);
        if (kk.w) atomicAdd(&cnt[w][mm.w], 1);
    }
    __syncthreads();
    if (tid < NTYPE) {
        int s = cnt[0][tid];
        #pragma unroll
        for (int b = 1; b < 8; b++) s += cnt[b][tid];
        cnt[0][tid] = s;
    }
    __syncthreads();

    const int half_id = tid >> 7;
    const int f = tid & 127;
    float acc = 0.f;
    if (f < DOUT) {
        float hw = 0.f;
        #pragma unroll 6
        for (int c = 0; c < H2; c++) hw = fmaf(hsh[c], W[c * DOUT + f], hw);
        float Wc[DEP];
        #pragma unroll
        for (int c = 0; c < DEP; c++) Wc[c] = W[(H2 + c) * DOUT + f];
        const float bf = bvec[f];

        __half* Tb = g_Th + (size_t)i * TPI;
        const int t0 = half_id * (NTYPE / 2), t1 = t0 + NTYPE / 2;
        #pragma unroll 5
        for (int t = t0; t < t1; t++) {
            float ew = bf;
            #pragma unroll
            for (int c = 0; c < DEP; c++) ew = fmaf(esh[t * DEP + c], Wc[c], ew);
            float v = fast_tanh(hw + ew);
            if (f < 64) Tb[t * 64 + f] = __float2half_rn(v);
            else        Tb[3200 + t * 8 + (f - 64)] = __float2half_rn(v);
            acc = fmaf((float)cnt[0][t], v, acc);
        }
        if (half_id == 0) sA[f] = acc;
    }
    __syncthreads();
    if (half_id == 1 && f < DOUT) {
        out[i * DOUT + f] = sA[f] + acc;        // s_in (fp32 path)
        out[NN * DOUT + i * DOUT + f] = 0.f;    // zero s_out for kernel C
    }
}

// ---------------------------------------------------------------------------
// Kernel C: s_out gather. Grid (8 j-tiles of 128, 37 i-tiles) = 296 blocks,
// 2 CTAs/SM. cp.async ping-pong stages fp16 T[i] (7.2KB). Codes in SMEM:
// code = (mask? t*128 : 6400) per slot, two slots packed per j. Branch-free
// sentinel rows. Main: lane l reads half2 at row+4l (dims 2l,2l+1) — one
// conflict-free wavefront per row. Tail: 8 slots per LDS, lane=(g=lane>>2,
// p=lane&3); p==3 lanes read the 2 pad halfs (accumulated, never stored).
// ---------------------------------------------------------------------------
#define IT 28
#define CTHREADS 512

__device__ __forceinline__ void cp16(unsigned dst, const void* src) {
    asm volatile("cp.async.cg.shared.global [%0], [%1], 16;" :: "r"(dst), "l"(src));
}

__global__ __launch_bounds__(CTHREADS, 2) void col_kernel(
    const int* __restrict__ matrix,
    const int* __restrict__ mask,
    float* __restrict__ sout)
{
    __shared__ __align__(16) __half Tsh[2][BUFH];
    __shared__ int codes[2][128];

    const int jbase = blockIdx.x * 128;
    const int i0 = blockIdx.y * IT;
    const int i1 = min(i0 + IT, NN);
    const int tid = threadIdx.x;
    const int w = tid >> 5, lane = tid & 31;
    const int g = lane >> 2, p = lane & 3;

    float2 a0[8];        // main dims (2*lane, 2*lane+1) for 8 j's
    float2 a1[2];        // tail pairs for slots g and 8+g
    #pragma unroll
    for (int q = 0; q < 8; q++) a0[q] = make_float2(0.f, 0.f);
    a1[0] = make_float2(0.f, 0.f);
    a1[1] = make_float2(0.f, 0.f);

    // zero sentinel regions (never touched by cp.async)
    {
        unsigned* z0 = (unsigned*)&Tsh[0][0];
        unsigned* z1 = (unsigned*)&Tsh[1][0];
        if (tid < 32) { z0[1600 + tid] = 0u; z1[1600 + tid] = 0u; }      // main sent 128B
        if (tid < 4)  { z0[1832 + tid] = 0u; z1[1832 + tid] = 0u; }      // tail sent 16B
    }

    const char* tb0 = (const char*)&Tsh[0][0];
    const char* tb1 = (const char*)&Tsh[1][0];
    const unsigned ts0 = (unsigned)__cvta_generic_to_shared(tb0);
    const unsigned ts1 = (unsigned)__cvta_generic_to_shared(tb1);

    const int2* m2 = (const int2*)matrix;
    const int2* k2 = (const int2*)mask;

    // prologue: stage i0 (main 400 cp16, tail 50 cp16)
    {
        const char* src = (const char*)(g_Th + (size_t)i0 * TPI);
        if (tid < 400) cp16(ts0 + tid * 16, src + tid * 16);
        else if (tid < 450) cp16(ts0 + TAIL_BASE_B + (tid - 400) * 16, src + 6400 + (tid - 400) * 16);
        asm volatile("cp.async.commit_group;");
    }
    int pcode = 0;
    if (tid < 128) {
        size_t idx = (size_t)i0 * NN + jbase + tid;
        int2 tt = m2[idx];
        int2 km = k2[idx];
        pcode = (km.x ? (tt.x << 7) : (int)MAIN_SENT_B) |
                ((km.y ? (tt.y << 7) : (int)MAIN_SENT_B) << 16);
    }

    for (int i = i0; i < i1; i++) {
        const int buf = (i - i0) & 1;
        const char* Tb = buf ? tb1 : tb0;

        asm volatile("cp.async.wait_group 0;" ::: "memory");  // T[i] landed
        if (tid < 128) codes[buf][tid] = pcode;
        __syncthreads();

        if (i + 1 < i1) {
            const unsigned dst = buf ? ts0 : ts1;
            const char* src = (const char*)(g_Th + (size_t)(i + 1) * TPI);
            if (tid < 400) cp16(dst + tid * 16, src + tid * 16);
            else if (tid < 450) cp16(dst + TAIL_BASE_B + (tid - 400) * 16, src + 6400 + (tid - 400) * 16);
            asm volatile("cp.async.commit_group;");
            if (tid < 128) {
                size_t idx = (size_t)(i + 1) * NN + jbase + tid;
                int2 tt = m2[idx];
                int2 km = k2[idx];
                pcode = (km.x ? (tt.x << 7) : (int)MAIN_SENT_B) |
                        ((km.y ? (tt.y << 7) : (int)MAIN_SENT_B) << 16);
            }
        }

        // main gather: 1 wavefront per row, sentinel for masked slots
        const int* cb = codes[buf];
        const int jb = w * 8;
        const char* mb = Tb + lane * 4;
        #pragma unroll
        for (int q = 0; q < 8; q++) {
            unsigned cc = (unsigned)cb[jb + q];   // warp-uniform broadcast
            unsigned o0 = cc & 0xFFFFu;
            unsigned o1 = cc >> 16;
            float2 v0 = __half22float2(*(const __half2*)(mb + o0));
            float2 v1 = __half22float2(*(const __half2*)(mb + o1));
            a0[q].x += v0.x + v1.x;
            a0[q].y += v0.y + v1.y;
        }

        // tail gather: slots s = r*8+g; lane reads pair p of row t(s).
        // t = code16 >> 7 (sentinel -> 50, the zero tail row).
        #pragma unroll
        for (int r = 0; r < 2; r++) {
            int s = r * 8 + g;
            unsigned cc = (unsigned)cb[jb + (s >> 1)];
            unsigned c16 = (s & 1) ? (cc >> 16) : (cc & 0xFFFFu);
            unsigned t = c16 >> 7;
            float2 v = __half22float2(*(const __half2*)(Tb + TAIL_BASE_B + t * 16 + p * 4));
            a1[r].x += v.x;
            a1[r].y += v.y;
        }
    }

    // epilogue: combine partials across the 37 i-tiles
    #pragma unroll
    for (int q = 0; q < 8; q++) {
        int j = jbase + w * 8 + q;
        float* base = sout + (size_t)j * DOUT;
        asm volatile("red.global.add.v2.f32 [%0], {%1, %2};"
                     :: "l"(base + 2 * lane), "f"(a0[q].x), "f"(a0[q].y) : "memory");
    }
    if (p < 3) {
        #pragma unroll
        for (int r = 0; r < 2; r++) {
            int s = r * 8 + g;
            int j = jbase + w * 8 + (s >> 1);
            float* base = sout + (size_t)j * DOUT + 64 + 2 * p;
            asm volatile("red.global.add.v2.f32 [%0], {%1, %2};"
                         :: "l"(base), "f"(a1[r].x), "f"(a1[r].y) : "memory");
        }
    }
}

// ---------------------------------------------------------------------------
extern "C" void kernel_launch(void* const* d_in, const int* in_sizes, int n_in,
                              void* d_out, int out_size)
{
    const float* h      = (const float*)d_in[0];
    const float* emb    = (const float*)d_in[1];
    const float* W      = (const float*)d_in[2];
    const float* bvec   = (const float*)d_in[3];
    const int*   matrix = (const int*)d_in[4];
    const int*   mask   = (const int*)d_in[5];
    float* out = (float*)d_out;

    row_kernel<<<NN, 256>>>(h, emb, W, bvec, matrix, mask, out);
    col_kernel<<<dim3(8, 37), CTHREADS>>>(matrix, mask, out + NN * DOUT);
}

// round 9
// speedup vs baseline: 2.4672x; 1.1742x over previous
#include <cuda_runtime.h>
#include <cuda_fp16.h>
#include <cstdint>

#define NN 1024
#define H2 60
#define DEP 10
#define DOUT 70
#define NTYPE 50

// fp16 T layout per i: main = dims 0..63, 50 rows x 64 halfs (128B rows);
// tail = dims 64..69 (+2 pad), 50 rows x 8 halfs (16B rows).
// Global block per i = 3200 + 400 = 3600 halfs = 7200B.
#define TPI 3600
// SMEM per i-slot (halfs): [0,3200) main, [3200,3264) main sentinel,
// [3264,3664) tail, [3664,3672) tail sentinel, pad to 3680 (7360B).
#define BUFH 3680
#define SLOTB 7360            // bytes per i-slot
#define MAIN_SENT_B 6400u     // byte offset of main sentinel row within slot
#define TAIL_BASE_B 6528      // byte offset of tail region within slot

__device__ __half g_Th[NN * TPI];    // 7.37 MB — L2-resident

// tanh(x) = 1 - 2/(exp(2x)+1), via SFU ex2/rcp.
__device__ __forceinline__ float fast_tanh(float x) {
    float e, r;
    asm("ex2.approx.f32 %0, %1;" : "=f"(e) : "f"(x * 2.885390082f));
    asm("rcp.approx.f32 %0, %1;" : "=f"(r) : "f"(e + 1.0f));
    return fmaf(-2.0f, r, 1.0f);
}

// ---------------------------------------------------------------------------
// Kernel R (block = row i, 288 threads = 4 groups x 72): masked histogram,
// hW once into SMEM, T table (fp16 split), s_in via 4-way partials,
// zero s_out row i.
// ---------------------------------------------------------------------------
__global__ __launch_bounds__(288) void row_kernel(
    const float* __restrict__ h,
    const float* __restrict__ emb,
    const float* __restrict__ W,
    const float* __restrict__ bvec,
    const int* __restrict__ matrix,
    const int* __restrict__ mask,
    float* __restrict__ out)
{
    const int i = blockIdx.x;
    const int tid = threadIdx.x;
    const int w = tid >> 5;

    __shared__ int   cnt[9][64];
    __shared__ float hsh[H2];
    __shared__ float esh[NTYPE * DEP];
    __shared__ float hwsh[72];
    __shared__ float sP[4][72];

    for (int k = tid; k < 9 * 64; k += 288) ((int*)cnt)[k] = 0;
    if (tid < H2) hsh[tid] = h[i * H2 + tid];
    for (int k = tid; k < NTYPE * DEP; k += 288) esh[k] = emb[k];
    __syncthreads();

    // masked type histogram (int4 loads, warp-private counters)
    const int4* m4 = (const int4*)(matrix + (size_t)i * 2 * NN);
    const int4* k4 = (const int4*)(mask   + (size_t)i * 2 * NN);
    for (int e = tid; e < 512; e += 288) {
        int4 mm = m4[e];
        int4 kk = k4[e];
        if (kk.x) atomicAdd(&cnt[w][mm.x], 1);
        if (kk.y) atomicAdd(&cnt[w][mm.y], 1);
        if (kk.z) atomicAdd(&cnt[w][mm.z], 1);
        if (kk.w) atomicAdd(&cnt[w][mm.w], 1);
    }
    // hW[i][f] once (group 0 computes, all read)
    if (tid < DOUT) {
        float hw = 0.f;
        #pragma unroll 6
        for (int c = 0; c < H2; c++) hw = fmaf(hsh[c], W[c * DOUT + tid], hw);
        hwsh[tid] = hw;
    }
    __syncthreads();
    if (tid < NTYPE) {
        int s = cnt[0][tid];
        #pragma unroll
        for (int b = 1; b < 9; b++) s += cnt[b][tid];
        cnt[0][tid] = s;
    }
    __syncthreads();

    const int grp = tid / 72;          // 0..3
    const int f = tid - grp * 72;      // 0..71
    float acc = 0.f;
    if (f < DOUT) {
        const float hw = hwsh[f];
        float Wc[DEP];
        #pragma unroll
        for (int c = 0; c < DEP; c++) Wc[c] = W[(H2 + c) * DOUT + f];
        const float bf = bvec[f];

        __half* Tb = g_Th + (size_t)i * TPI;
        const int t0 = grp * 13;
        const int t1 = (t0 + 13 < NTYPE) ? t0 + 13 : NTYPE;
        for (int t = t0; t < t1; t++) {
            float ew = bf;
            #pragma unroll
            for (int c = 0; c < DEP; c++) ew = fmaf(esh[t * DEP + c], Wc[c], ew);
            float v = fast_tanh(hw + ew);
            if (f < 64) Tb[t * 64 + f] = __float2half_rn(v);
            else        Tb[3200 + t * 8 + (f - 64)] = __float2half_rn(v);
            acc = fmaf((float)cnt[0][t], v, acc);
        }
    }
    sP[grp][f] = acc;
    __syncthreads();
    if (grp == 0 && f < DOUT) {
        float s = sP[0][f] + sP[1][f] + sP[2][f] + sP[3][f];
        out[i * DOUT + f] = s;                  // s_in (fp32 path)
        out[NN * DOUT + i * DOUT + f] = 0.f;    // zero s_out for kernel C
    }
}

// ---------------------------------------------------------------------------
// Kernel C: s_out gather. Grid (8 j-tiles of 128, 37 i-tiles) = 296 blocks,
// 2 CTAs/SM. cp.async ping-pong stages TWO i-rows per stage (2 x 7.2KB).
// Codes in SMEM, branch-free sentinel rows. Main: lane l reads half2 at
// row+4l (1 conflict-free wavefront/row); pair-sum in fp16 (HADD2) before
// conversion. Tail: 8 slots per LDS.
// ---------------------------------------------------------------------------
#define IT 28
#define CTHREADS 512

__device__ __forceinline__ void cp16(unsigned dst, const void* src) {
    asm volatile("cp.async.cg.shared.global [%0], [%1], 16;" :: "r"(dst), "l"(src));
}

// stage both i-slots of one pipeline stage (900 x 16B)
__device__ __forceinline__ void stage2(unsigned dst, const char* src, int tid) {
    #pragma unroll
    for (int s = 0; s < 2; s++) {
        if (tid < 400) cp16(dst + s * SLOTB + tid * 16, src + s * 7200 + tid * 16);
        else if (tid < 450) cp16(dst + s * SLOTB + TAIL_BASE_B + (tid - 400) * 16,
                                 src + s * 7200 + 6400 + (tid - 400) * 16);
    }
}

__global__ __launch_bounds__(CTHREADS, 2) void col_kernel(
    const int* __restrict__ matrix,
    const int* __restrict__ mask,
    float* __restrict__ sout)
{
    __shared__ __align__(16) __half Tsh[2][2 * BUFH];
    __shared__ int codes[2][256];

    const int jbase = blockIdx.x * 128;
    const int i0 = blockIdx.y * IT;
    const int i1 = min(i0 + IT, NN);
    const int nst = (i1 - i0) >> 1;          // stages of 2 i's (always even here)
    const int tid = threadIdx.x;
    const int w = tid >> 5, lane = tid & 31;
    const int g = lane >> 2, p = lane & 3;

    float2 a0[8];        // main dims (2*lane, 2*lane+1) for the warp's 8 j's
    float2 a1[2];        // tail pairs for slots g and 8+g
    #pragma unroll
    for (int q = 0; q < 8; q++) a0[q] = make_float2(0.f, 0.f);
    a1[0] = make_float2(0.f, 0.f);
    a1[1] = make_float2(0.f, 0.f);

    // zero sentinel regions (word granularity); never touched by cp.async
    if (tid < 128) {
        int b = tid >> 6, rest = tid & 63, s = rest >> 5, k = rest & 31;
        ((unsigned*)&Tsh[b][0])[s * 1840 + 1600 + k] = 0u;   // main sentinel 128B
    }
    if (tid < 16) {
        int b = tid >> 3, s = (tid >> 2) & 1, k = tid & 3;
        ((unsigned*)&Tsh[b][0])[s * 1840 + 1832 + k] = 0u;   // tail sentinel 16B
    }

    const char* tb0 = (const char*)&Tsh[0][0];
    const char* tb1 = (const char*)&Tsh[1][0];
    const unsigned ts0 = (unsigned)__cvta_generic_to_shared(tb0);
    const unsigned ts1 = (unsigned)__cvta_generic_to_shared(tb1);

    const int2* m2 = (const int2*)matrix;
    const int2* k2 = (const int2*)mask;

    // prologue: stage (i0, i0+1)
    stage2(ts0, (const char*)(g_Th + (size_t)i0 * TPI), tid);
    asm volatile("cp.async.commit_group;");

    int pcode = 0;
    if (tid < 256) {
        int ii = tid >> 7, jj = tid & 127;
        size_t idx = (size_t)(i0 + ii) * NN + jbase + jj;
        int2 tt = m2[idx];
        int2 km = k2[idx];
        pcode = (km.x ? (tt.x << 7) : (int)MAIN_SENT_B) |
                ((km.y ? (tt.y << 7) : (int)MAIN_SENT_B) << 16);
    }

    for (int st = 0; st < nst; st++) {
        const int buf = st & 1;
        const char* Tbb = buf ? tb1 : tb0;

        asm volatile("cp.async.wait_group 0;" ::: "memory");  // stage landed
        if (tid < 256) codes[buf][tid] = pcode;
        __syncthreads();

        if (st + 1 < nst) {
            const int inext = i0 + 2 * (st + 1);
            stage2(buf ? ts0 : ts1, (const char*)(g_Th + (size_t)inext * TPI), tid);
            asm volatile("cp.async.commit_group;");
            if (tid < 256) {
                int ii = tid >> 7, jj = tid & 127;
                size_t idx = (size_t)(inext + ii) * NN + jbase + jj;
                int2 tt = m2[idx];
                int2 km = k2[idx];
                pcode = (km.x ? (tt.x << 7) : (int)MAIN_SENT_B) |
                        ((km.y ? (tt.y << 7) : (int)MAIN_SENT_B) << 16);
            }
        }

        // gather both i-slots of this stage
        #pragma unroll
        for (int s2 = 0; s2 < 2; s2++) {
            const char* Tb = Tbb + s2 * SLOTB;
            const int* cb = codes[buf] + s2 * 128 + w * 8;
            const char* mb = Tb + lane * 4;
            #pragma unroll
            for (int q = 0; q < 8; q++) {
                unsigned cc = (unsigned)cb[q];   // warp-uniform broadcast
                unsigned o0 = cc & 0xFFFFu;
                unsigned o1 = cc >> 16;
                __half2 h0 = *(const __half2*)(mb + o0);
                __half2 h1 = *(const __half2*)(mb + o1);
                float2 v = __half22float2(__hadd2(h0, h1));
                a0[q].x += v.x;
                a0[q].y += v.y;
            }
            // tail: slots s = r*8+g; lane reads pair p of row t(s)
            #pragma unroll
            for (int r = 0; r < 2; r++) {
                int s = r * 8 + g;
                unsigned cc = (unsigned)cb[s >> 1];
                unsigned c16 = (s & 1) ? (cc >> 16) : (cc & 0xFFFFu);
                unsigned t = c16 >> 7;           // type, or 50 for sentinel
                float2 v = __half22float2(*(const __half2*)(Tb + TAIL_BASE_B + t * 16 + p * 4));
                a1[r].x += v.x;
                a1[r].y += v.y;
            }
        }
    }

    // epilogue: combine partials across the 37 i-tiles
    #pragma unroll
    for (int q = 0; q < 8; q++) {
        int j = jbase + w * 8 + q;
        float* base = sout + (size_t)j * DOUT;
        asm volatile("red.global.add.v2.f32 [%0], {%1, %2};"
                     :: "l"(base + 2 * lane), "f"(a0[q].x), "f"(a0[q].y) : "memory");
    }
    if (p < 3) {
        #pragma unroll
        for (int r = 0; r < 2; r++) {
            int s = r * 8 + g;
            int j = jbase + w * 8 + (s >> 1);
            float* base = sout + (size_t)j * DOUT + 64 + 2 * p;
            asm volatile("red.global.add.v2.f32 [%0], {%1, %2};"
                         :: "l"(base), "f"(a1[r].x), "f"(a1[r].y) : "memory");
        }
    }
}

// ---------------------------------------------------------------------------
extern "C" void kernel_launch(void* const* d_in, const int* in_sizes, int n_in,
                              void* d_out, int out_size)
{
    const float* h      = (const float*)d_in[0];
    const float* emb    = (const float*)d_in[1];
    const float* W      = (const float*)d_in[2];
    const float* bvec   = (const float*)d_in[3];
    const int*   matrix = (const int*)d_in[4];
    const int*   mask   = (const int*)d_in[5];
    float* out = (float*)d_out;

    row_kernel<<<NN, 288>>>(h, emb, W, bvec, matrix, mask, out);
    col_kernel<<<dim3(8, 37), CTHREADS>>>(matrix, mask, out + NN * DOUT);
}

// round 10
// speedup vs baseline: 2.5633x; 1.0390x over previous
#include <cuda_runtime.h>
#include <cuda_fp16.h>
#include <cstdint>

#define NN 1024
#define H2 60
#define DEP 10
#define DOUT 70
#define NTYPE 50

// fp16 T layout per i: main = dims 0..63, 50 rows x 64 halfs (128B rows);
// tail = dims 64..69 (+2 pad), 50 rows x 8 halfs (16B rows).
#define TPI 3600
#define BUFH 3680
#define SLOTB 7360
#define MAIN_SENT_B 6400u
#define TAIL_BASE_B 6528

__device__ __half g_Th[NN * TPI];       // 7.37 MB — L2-resident
__device__ float  g_eWb[NTYPE * DOUT];  // 3500 floats, L1-hot everywhere

// tanh(x) = 1 - 2/(exp(2x)+1), via SFU ex2/rcp.
__device__ __forceinline__ float fast_tanh(float x) {
    float e, r;
    asm("ex2.approx.f32 %0, %1;" : "=f"(e) : "f"(x * 2.885390082f));
    asm("rcp.approx.f32 %0, %1;" : "=f"(r) : "f"(e + 1.0f));
    return fmaf(-2.0f, r, 1.0f);
}

// ---------------------------------------------------------------------------
// Kernel E: eWb[t][f] = b[f] + emb[t,:] @ W[H2:,f]   (3500 elems, once)
// ---------------------------------------------------------------------------
__global__ __launch_bounds__(256) void ewb_kernel(
    const float* __restrict__ emb,
    const float* __restrict__ W,
    const float* __restrict__ bvec)
{
    int k = blockIdx.x * 256 + threadIdx.x;
    if (k >= NTYPE * DOUT) return;
    int t = k / DOUT, f = k - t * DOUT;
    float s = bvec[f];
    #pragma unroll
    for (int c = 0; c < DEP; c++)
        s = fmaf(emb[t * DEP + c], W[(H2 + c) * DOUT + f], s);
    g_eWb[k] = s;
}

// ---------------------------------------------------------------------------
// Kernel R: 640 threads = 4 independent groups x 160 (5 warps). Group g of
// block B owns row i = B*4+g: warp-private histogram banks + named barriers
// (no block-wide sync), hW via __ldg, T table (fp16 split), s_in, zero s_out.
// Heavy phase: gtid = s*70+f (140 active), t-range split in two.
// ---------------------------------------------------------------------------
__global__ __launch_bounds__(640) void row_kernel(
    const float* __restrict__ h,
    const float* __restrict__ W,
    const int* __restrict__ matrix,
    const int* __restrict__ mask,
    float* __restrict__ out)
{
    const int tid = threadIdx.x;
    const int grp = tid / 160;
    const int gtid = tid - grp * 160;
    const int w = tid >> 5;            // global warp id 0..19
    const int lane = tid & 31;
    const int i = blockIdx.x * 4 + grp;
    const int bar = grp + 1;

    __shared__ int   cnt[20][64];      // warp-private histogram banks
    __shared__ float sP[4][72];

    // zero own warp's bank
    cnt[w][lane] = 0;
    cnt[w][lane + 32] = 0;
    asm volatile("bar.sync %0, 160;" :: "r"(bar) : "memory");

    // masked type histogram over row i (int4 loads)
    {
        const int4* m4 = (const int4*)(matrix + (size_t)i * 2 * NN);
        const int4* k4 = (const int4*)(mask   + (size_t)i * 2 * NN);
        for (int e = gtid; e < 512; e += 160) {
            int4 mm = m4[e];
            int4 kk = k4[e];
            if (kk.x) atomicAdd(&cnt[w][mm.x], 1);
            if (kk.y) atomicAdd(&cnt[w][mm.y], 1);
            if (kk.z) atomicAdd(&cnt[w][mm.z], 1);
            if (kk.w) atomicAdd(&cnt[w][mm.w], 1);
        }
    }
    asm volatile("bar.sync %0, 160;" :: "r"(bar) : "memory");

    // reduce the group's 5 banks into bank grp*5
    const int b0 = grp * 5;
    if (gtid < NTYPE) {
        int s = cnt[b0][gtid] + cnt[b0 + 1][gtid] + cnt[b0 + 2][gtid]
              + cnt[b0 + 3][gtid] + cnt[b0 + 4][gtid];
        cnt[b0][gtid] = s;
    }
    asm volatile("bar.sync %0, 160;" :: "r"(bar) : "memory");

    // heavy phase: 140 active threads, (s, f) with t split in halves
    const int shalf = gtid / DOUT;     // 0,1 (2 for inactive tail)
    const int f = gtid - shalf * DOUT;
    float acc = 0.f;
    if (shalf < 2) {
        float hw = 0.f;
        #pragma unroll 6
        for (int c = 0; c < H2; c++)
            hw = fmaf(__ldg(h + i * H2 + c), __ldg(W + c * DOUT + f), hw);

        __half* Tb = g_Th + (size_t)i * TPI;
        const int t0 = shalf * 25, t1 = t0 + 25;
        #pragma unroll 5
        for (int t = t0; t < t1; t++) {
            float ew = __ldg(g_eWb + t * DOUT + f);
            float v = fast_tanh(hw + ew);
            if (f < 64) Tb[t * 64 + f] = __float2half_rn(v);
            else        Tb[3200 + t * 8 + (f - 64)] = __float2half_rn(v);
            acc = fmaf((float)cnt[b0][t], v, acc);
        }
        if (shalf == 1) sP[grp][f] = acc;
    }
    asm volatile("bar.sync %0, 160;" :: "r"(bar) : "memory");
    if (shalf == 0) {
        out[i * DOUT + f] = acc + sP[grp][f];   // s_in (fp32)
        out[NN * DOUT + i * DOUT + f] = 0.f;    // zero s_out for kernel C
    }
}

// ---------------------------------------------------------------------------
// Kernel C: s_out gather (UNCHANGED from R8 — 27.1us, protect it).
// ---------------------------------------------------------------------------
#define IT 28
#define CTHREADS 512

__device__ __forceinline__ void cp16(unsigned dst, const void* src) {
    asm volatile("cp.async.cg.shared.global [%0], [%1], 16;" :: "r"(dst), "l"(src));
}

__device__ __forceinline__ void stage2(unsigned dst, const char* src, int tid) {
    #pragma unroll
    for (int s = 0; s < 2; s++) {
        if (tid < 400) cp16(dst + s * SLOTB + tid * 16, src + s * 7200 + tid * 16);
        else if (tid < 450) cp16(dst + s * SLOTB + TAIL_BASE_B + (tid - 400) * 16,
                                 src + s * 7200 + 6400 + (tid - 400) * 16);
    }
}

__global__ __launch_bounds__(CTHREADS, 2) void col_kernel(
    const int* __restrict__ matrix,
    const int* __restrict__ mask,
    float* __restrict__ sout)
{
    __shared__ __align__(16) __half Tsh[2][2 * BUFH];
    __shared__ int codes[2][256];

    const int jbase = blockIdx.x * 128;
    const int i0 = blockIdx.y * IT;
    const int i1 = min(i0 + IT, NN);
    const int nst = (i1 - i0) >> 1;
    const int tid = threadIdx.x;
    const int w = tid >> 5, lane = tid & 31;
    const int g = lane >> 2, p = lane & 3;

    float2 a0[8];
    float2 a1[2];
    #pragma unroll
    for (int q = 0; q < 8; q++) a0[q] = make_float2(0.f, 0.f);
    a1[0] = make_float2(0.f, 0.f);
    a1[1] = make_float2(0.f, 0.f);

    if (tid < 128) {
        int b = tid >> 6, rest = tid & 63, s = rest >> 5, k = rest & 31;
        ((unsigned*)&Tsh[b][0])[s * 1840 + 1600 + k] = 0u;
    }
    if (tid < 16) {
        int b = tid >> 3, s = (tid >> 2) & 1, k = tid & 3;
        ((unsigned*)&Tsh[b][0])[s * 1840 + 1832 + k] = 0u;
    }

    const char* tb0 = (const char*)&Tsh[0][0];
    const char* tb1 = (const char*)&Tsh[1][0];
    const unsigned ts0 = (unsigned)__cvta_generic_to_shared(tb0);
    const unsigned ts1 = (unsigned)__cvta_generic_to_shared(tb1);

    const int2* m2 = (const int2*)matrix;
    const int2* k2 = (const int2*)mask;

    stage2(ts0, (const char*)(g_Th + (size_t)i0 * TPI), tid);
    asm volatile("cp.async.commit_group;");

    int pcode = 0;
    if (tid < 256) {
        int ii = tid >> 7, jj = tid & 127;
        size_t idx = (size_t)(i0 + ii) * NN + jbase + jj;
        int2 tt = m2[idx];
        int2 km = k2[idx];
        pcode = (km.x ? (tt.x << 7) : (int)MAIN_SENT_B) |
                ((km.y ? (tt.y << 7) : (int)MAIN_SENT_B) << 16);
    }

    for (int st = 0; st < nst; st++) {
        const int buf = st & 1;
        const char* Tbb = buf ? tb1 : tb0;

        asm volatile("cp.async.wait_group 0;" ::: "memory");
        if (tid < 256) codes[buf][tid] = pcode;
        __syncthreads();

        if (st + 1 < nst) {
            const int inext = i0 + 2 * (st + 1);
            stage2(buf ? ts0 : ts1, (const char*)(g_Th + (size_t)inext * TPI), tid);
            asm volatile("cp.async.commit_group;");
            if (tid < 256) {
                int ii = tid >> 7, jj = tid & 127;
                size_t idx = (size_t)(inext + ii) * NN + jbase + jj;
                int2 tt = m2[idx];
                int2 km = k2[idx];
                pcode = (km.x ? (tt.x << 7) : (int)MAIN_SENT_B) |
                        ((km.y ? (tt.y << 7) : (int)MAIN_SENT_B) << 16);
            }
        }

        #pragma unroll
        for (int s2 = 0; s2 < 2; s2++) {
            const char* Tb = Tbb + s2 * SLOTB;
            const int* cb = codes[buf] + s2 * 128 + w * 8;
            const char* mb = Tb + lane * 4;
            #pragma unroll
            for (int q = 0; q < 8; q++) {
                unsigned cc = (unsigned)cb[q];
                unsigned o0 = cc & 0xFFFFu;
                unsigned o1 = cc >> 16;
                __half2 h0 = *(const __half2*)(mb + o0);
                __half2 h1 = *(const __half2*)(mb + o1);
                float2 v = __half22float2(__hadd2(h0, h1));
                a0[q].x += v.x;
                a0[q].y += v.y;
            }
            #pragma unroll
            for (int r = 0; r < 2; r++) {
                int s = r * 8 + g;
                unsigned cc = (unsigned)cb[s >> 1];
                unsigned c16 = (s & 1) ? (cc >> 16) : (cc & 0xFFFFu);
                unsigned t = c16 >> 7;
                float2 v = __half22float2(*(const __half2*)(Tb + TAIL_BASE_B + t * 16 + p * 4));
                a1[r].x += v.x;
                a1[r].y += v.y;
            }
        }
    }

    #pragma unroll
    for (int q = 0; q < 8; q++) {
        int j = jbase + w * 8 + q;
        float* base = sout + (size_t)j * DOUT;
        asm volatile("red.global.add.v2.f32 [%0], {%1, %2};"
                     :: "l"(base + 2 * lane), "f"(a0[q].x), "f"(a0[q].y) : "memory");
    }
    if (p < 3) {
        #pragma unroll
        for (int r = 0; r < 2; r++) {
            int s = r * 8 + g;
            int j = jbase + w * 8 + (s >> 1);
            float* base = sout + (size_t)j * DOUT + 64 + 2 * p;
            asm volatile("red.global.add.v2.f32 [%0], {%1, %2};"
                         :: "l"(base), "f"(a1[r].x), "f"(a1[r].y) : "memory");
        }
    }
}

// ---------------------------------------------------------------------------
extern "C" void kernel_launch(void* const* d_in, const int* in_sizes, int n_in,
                              void* d_out, int out_size)
{
    const float* h      = (const float*)d_in[0];
    const float* emb    = (const float*)d_in[1];
    const float* W      = (const float*)d_in[2];
    const float* bvec   = (const float*)d_in[3];
    const int*   matrix = (const int*)d_in[4];
    const int*   mask   = (const int*)d_in[5];
    float* out = (float*)d_out;

    ewb_kernel<<<14, 256>>>(emb, W, bvec);
    row_kernel<<<NN / 4, 640>>>(h, W, matrix, mask, out);
    col_kernel<<<dim3(8, 37), CTHREADS>>>(matrix, mask, out + NN * DOUT);
}